// round 1
// baseline (speedup 1.0000x reference)
#include <cuda_runtime.h>
#include <math.h>

#define BB 4
#define TT 4096
#define DD 1024
#define NO 256      // 2*dv
#define NROW (BB*TT)
#define LN_EPS_F 1e-5f
#define LAMBDA_INIT 0.3555090675909693f
#define ATT_SCALE 0.0883883476483184405f   // 1/sqrt(128)

// scratch (device globals: allocation-free rule)
__device__ float g_Q[NROW * NO];
__device__ float g_K[NROW * NO];
__device__ float g_V[NROW * NO];
__device__ float g_lambda;

// ---------------------------------------------------------------------------
// Kernel 1: uniform QKV GEMM.  C[16384 x 768] = X[16384 x 1024] @ {Wq|Wk|Wv}
// BM=64 BN=64 BK=16, 256 threads, 4x4 micro-tile.
// ---------------------------------------------------------------------------
__global__ __launch_bounds__(256) void qkv_gemm(
    const float* __restrict__ x,
    const float* __restrict__ Wq,
    const float* __restrict__ Wk,
    const float* __restrict__ Wv)
{
    __shared__ float Xs[16][68];   // [k][m], padded
    __shared__ float Ws[16][64];   // [k][n]

    const int nt  = blockIdx.x;          // 0..11
    const int mt  = blockIdx.y;          // 0..255
    const int mat = nt >> 2;             // 0=Q,1=K,2=V
    const int n0  = (nt & 3) * 64;
    const float* W = (mat == 0) ? Wq : ((mat == 1) ? Wk : Wv);
    float* Out     = (mat == 0) ? g_Q : ((mat == 1) ? g_K : g_V);

    const int m0 = mt * 64;
    const int tx = threadIdx.x;          // 0..15
    const int ty = threadIdx.y;          // 0..15
    const int tid = ty * 16 + tx;

    float c[4][4];
#pragma unroll
    for (int i = 0; i < 4; i++)
#pragma unroll
        for (int j = 0; j < 4; j++) c[i][j] = 0.f;

    for (int k0 = 0; k0 < DD; k0 += 16) {
        // X tile: 64 rows x 16 cols
        {
            int row = tid >> 2;          // 0..63
            int c4  = tid & 3;           // 0..3
            float4 xv = *(const float4*)(x + (size_t)(m0 + row) * DD + k0 + c4 * 4);
            Xs[c4 * 4 + 0][row] = xv.x;
            Xs[c4 * 4 + 1][row] = xv.y;
            Xs[c4 * 4 + 2][row] = xv.z;
            Xs[c4 * 4 + 3][row] = xv.w;
        }
        // W tile: 16 rows x 64 cols
        {
            int kr = tid >> 4;           // 0..15
            int c4 = tid & 15;           // 0..15
            float4 wv = *(const float4*)(W + (size_t)(k0 + kr) * NO + n0 + c4 * 4);
            *(float4*)(&Ws[kr][c4 * 4]) = wv;
        }
        __syncthreads();

#pragma unroll
        for (int kk = 0; kk < 16; kk++) {
            float4 a = *(const float4*)(&Xs[kk][ty * 4]);
            float4 b = *(const float4*)(&Ws[kk][tx * 4]);
            c[0][0] += a.x * b.x; c[0][1] += a.x * b.y; c[0][2] += a.x * b.z; c[0][3] += a.x * b.w;
            c[1][0] += a.y * b.x; c[1][1] += a.y * b.y; c[1][2] += a.y * b.z; c[1][3] += a.y * b.w;
            c[2][0] += a.z * b.x; c[2][1] += a.z * b.y; c[2][2] += a.z * b.z; c[2][3] += a.z * b.w;
            c[3][0] += a.w * b.x; c[3][1] += a.w * b.y; c[3][2] += a.w * b.z; c[3][3] += a.w * b.w;
        }
        __syncthreads();
    }

#pragma unroll
    for (int i = 0; i < 4; i++) {
        float4 o = make_float4(c[i][0], c[i][1], c[i][2], c[i][3]);
        *(float4*)(Out + (size_t)(m0 + ty * 4 + i) * NO + n0 + tx * 4) = o;
    }
}

// ---------------------------------------------------------------------------
// Kernel 2: recompute the 64 state rows (first/last 8 tokens per batch)
// with the *_state weights.
// ---------------------------------------------------------------------------
__global__ __launch_bounds__(256) void state_fixup(
    const float* __restrict__ x,
    const float* __restrict__ Wqs,
    const float* __restrict__ Wks,
    const float* __restrict__ Wvs)
{
    __shared__ float xs[DD];
    const int id = blockIdx.x;             // 0..63
    const int b  = id >> 4;
    const int i  = id & 15;
    const int t  = (i < 8) ? i : (TT - 16 + i);
    const size_t row = (size_t)b * TT + t;
    const int tid = threadIdx.x;           // 0..255

    for (int d = tid; d < DD; d += 256) xs[d] = x[row * DD + d];
    __syncthreads();

    float aq = 0.f, ak = 0.f, av = 0.f;
    const int n = tid;
#pragma unroll 4
    for (int d = 0; d < DD; d++) {
        float xv = xs[d];
        aq += xv * Wqs[(size_t)d * NO + n];
        ak += xv * Wks[(size_t)d * NO + n];
        av += xv * Wvs[(size_t)d * NO + n];
    }
    g_Q[row * NO + n] = aq;
    g_K[row * NO + n] = ak;
    g_V[row * NO + n] = av;
}

// ---------------------------------------------------------------------------
// Kernel 3: lambda scalar
// ---------------------------------------------------------------------------
__global__ void lambda_kernel(const float* __restrict__ lq1,
                              const float* __restrict__ lq2,
                              const float* __restrict__ lk1,
                              const float* __restrict__ lk2)
{
    int lane = threadIdx.x;
    float s1 = 0.f, s2 = 0.f;
    for (int i = lane; i < 128; i += 32) {
        s1 += lq1[i] * lk1[i];
        s2 += lq2[i] * lk2[i];
    }
#pragma unroll
    for (int o = 16; o > 0; o >>= 1) {
        s1 += __shfl_xor_sync(0xffffffffu, s1, o);
        s2 += __shfl_xor_sync(0xffffffffu, s2, o);
    }
    if (lane == 0) g_lambda = expf(s1) - expf(s2) + LAMBDA_INIT;
}

// ---------------------------------------------------------------------------
// Kernel 4: fused differential causal attention + combine + LayerNorm.
// CTA = 256 threads (8 warps), 16 query rows (2 per warp), 32-key chunks.
// ---------------------------------------------------------------------------
__device__ __forceinline__ void fma4(float4& a, float w, const float4& v) {
    a.x += w * v.x; a.y += w * v.y; a.z += w * v.z; a.w += w * v.w;
}
__device__ __forceinline__ void scale4(float4& a, float c) {
    a.x *= c; a.y *= c; a.z *= c; a.w *= c;
}

// smem layout (float4 units): qs[16*64] | ks[32*65] | vs[32*64]
#define SM_QS 0
#define SM_KS (16 * 64)
#define SM_VS (16 * 64 + 32 * 65)
#define SM_TOTAL_F4 (16 * 64 + 32 * 65 + 32 * 64)

__global__ __launch_bounds__(256, 2) void attn_kernel(
    float* __restrict__ out,
    const float* __restrict__ ln_gamma,
    const float* __restrict__ ln_beta)
{
    extern __shared__ float4 sm[];
    float4* qs = sm + SM_QS;
    float4* ks = sm + SM_KS;
    float4* vs = sm + SM_VS;

    const int b   = blockIdx.y;
    const int t0  = blockIdx.x * 16;
    const int tid = threadIdx.x;
    const int warp = tid >> 5;
    const int lane = tid & 31;
    const size_t base = (size_t)b * TT;

    // load Q tile (16 rows x 256 floats)
    for (int idx = tid; idx < 16 * 64; idx += 256) {
        int r  = idx >> 6;
        int d4 = idx & 63;
        qs[idx] = *(const float4*)(g_Q + (base + t0 + r) * NO + d4 * 4);
    }

    const int r0  = warp * 2;
    const int tg0 = t0 + r0;
    const int tg1 = tg0 + 1;

    float m[2][2], l[2][2];
    float4 acc[2][2][2];   // [head][row][half]
#pragma unroll
    for (int h = 0; h < 2; h++)
#pragma unroll
        for (int r = 0; r < 2; r++) {
            m[h][r] = -INFINITY;
            l[h][r] = 0.f;
            acc[h][r][0] = make_float4(0.f, 0.f, 0.f, 0.f);
            acc[h][r][1] = make_float4(0.f, 0.f, 0.f, 0.f);
        }

    const int nch = (t0 + 16 + 31) >> 5;
    for (int c = 0; c < nch; c++) {
        const int kb = c << 5;
        __syncthreads();
        // load K/V chunk (32 keys)
        for (int idx = tid; idx < 32 * 64; idx += 256) {
            int key = idx >> 6;
            int d4  = idx & 63;
            int kr  = kb + key;
            float4 kv, vv;
            if (kr < TT) {
                kv = *(const float4*)(g_K + (base + kr) * NO + d4 * 4);
                vv = *(const float4*)(g_V + (base + kr) * NO + d4 * 4);
            } else {
                kv = make_float4(0.f, 0.f, 0.f, 0.f);
                vv = kv;
            }
            ks[key * 65 + d4] = kv;
            vs[key * 64 + d4] = vv;
        }
        __syncthreads();

        if (kb <= tg1) {
            // scores for both heads, both rows
            float sc[2][2];
#pragma unroll
            for (int h = 0; h < 2; h++) {
                float s0 = 0.f, s1 = 0.f;
                const float4* kp  = ks + lane * 65 + h * 32;
                const float4* q0p = qs + r0 * 64 + h * 32;
                const float4* q1p = q0p + 64;
#pragma unroll
                for (int d4 = 0; d4 < 32; d4++) {
                    float4 kf = kp[d4];
                    float4 qa = q0p[d4];
                    float4 qb = q1p[d4];
                    s0 += kf.x * qa.x + kf.y * qa.y + kf.z * qa.z + kf.w * qa.w;
                    s1 += kf.x * qb.x + kf.y * qb.y + kf.z * qb.z + kf.w * qb.w;
                }
                sc[h][0] = s0 * ATT_SCALE;
                sc[h][1] = s1 * ATT_SCALE;
            }

            const int key = kb + lane;
            float pw[2][2];
#pragma unroll
            for (int h = 0; h < 2; h++) {
#pragma unroll
                for (int ri = 0; ri < 2; ri++) {
                    const int tg = ri ? tg1 : tg0;
                    float s = sc[h][ri];
                    if (key > tg) s = -INFINITY;
                    float wm = s;
#pragma unroll
                    for (int o = 16; o > 0; o >>= 1)
                        wm = fmaxf(wm, __shfl_xor_sync(0xffffffffu, wm, o));
                    if (kb <= tg) {
                        float newm = fmaxf(m[h][ri], wm);
                        float p    = __expf(s - newm);
                        float corr = __expf(m[h][ri] - newm);
                        float psum = p;
#pragma unroll
                        for (int o = 16; o > 0; o >>= 1)
                            psum += __shfl_xor_sync(0xffffffffu, psum, o);
                        l[h][ri] = l[h][ri] * corr + psum;
                        m[h][ri] = newm;
                        scale4(acc[h][ri][0], corr);
                        scale4(acc[h][ri][1], corr);
                        pw[h][ri] = p;
                    } else {
                        pw[h][ri] = 0.f;
                    }
                }
            }

            // P @ V, shared V reads across heads/rows
#pragma unroll 8
            for (int j = 0; j < 32; j++) {
                float4 v0 = vs[j * 64 + lane];
                float4 v1 = vs[j * 64 + 32 + lane];
                float w;
                w = __shfl_sync(0xffffffffu, pw[0][0], j);
                fma4(acc[0][0][0], w, v0); fma4(acc[0][0][1], w, v1);
                w = __shfl_sync(0xffffffffu, pw[0][1], j);
                fma4(acc[0][1][0], w, v0); fma4(acc[0][1][1], w, v1);
                w = __shfl_sync(0xffffffffu, pw[1][0], j);
                fma4(acc[1][0][0], w, v0); fma4(acc[1][0][1], w, v1);
                w = __shfl_sync(0xffffffffu, pw[1][1], j);
                fma4(acc[1][1][0], w, v0); fma4(acc[1][1][1], w, v1);
            }
        }
    }

    // epilogue: combine + LayerNorm
    const float lamv = g_lambda;
    const float4 gm0 = *(const float4*)(ln_gamma + lane * 4);
    const float4 gm1 = *(const float4*)(ln_gamma + 128 + lane * 4);
    const float4 bt0 = *(const float4*)(ln_beta + lane * 4);
    const float4 bt1 = *(const float4*)(ln_beta + 128 + lane * 4);

#pragma unroll
    for (int ri = 0; ri < 2; ri++) {
        const int tg = t0 + r0 + ri;
        float i1 = 1.f / l[0][ri];
        float i2 = lamv / l[1][ri];
        float4 a0, a1;
        a0.x = acc[0][ri][0].x * i1 - acc[1][ri][0].x * i2;
        a0.y = acc[0][ri][0].y * i1 - acc[1][ri][0].y * i2;
        a0.z = acc[0][ri][0].z * i1 - acc[1][ri][0].z * i2;
        a0.w = acc[0][ri][0].w * i1 - acc[1][ri][0].w * i2;
        a1.x = acc[0][ri][1].x * i1 - acc[1][ri][1].x * i2;
        a1.y = acc[0][ri][1].y * i1 - acc[1][ri][1].y * i2;
        a1.z = acc[0][ri][1].z * i1 - acc[1][ri][1].z * i2;
        a1.w = acc[0][ri][1].w * i1 - acc[1][ri][1].w * i2;

        float s = a0.x + a0.y + a0.z + a0.w + a1.x + a1.y + a1.z + a1.w;
#pragma unroll
        for (int o = 16; o > 0; o >>= 1) s += __shfl_xor_sync(0xffffffffu, s, o);
        float mu = s * (1.f / 256.f);

        float q = 0.f;
        q += (a0.x - mu) * (a0.x - mu); q += (a0.y - mu) * (a0.y - mu);
        q += (a0.z - mu) * (a0.z - mu); q += (a0.w - mu) * (a0.w - mu);
        q += (a1.x - mu) * (a1.x - mu); q += (a1.y - mu) * (a1.y - mu);
        q += (a1.z - mu) * (a1.z - mu); q += (a1.w - mu) * (a1.w - mu);
#pragma unroll
        for (int o = 16; o > 0; o >>= 1) q += __shfl_xor_sync(0xffffffffu, q, o);
        float var  = q * (1.f / 256.f);
        float rstd = rsqrtf(var + LN_EPS_F);

        float4 o0, o1;
        o0.x = (a0.x - mu) * rstd * gm0.x + bt0.x;
        o0.y = (a0.y - mu) * rstd * gm0.y + bt0.y;
        o0.z = (a0.z - mu) * rstd * gm0.z + bt0.z;
        o0.w = (a0.w - mu) * rstd * gm0.w + bt0.w;
        o1.x = (a1.x - mu) * rstd * gm1.x + bt1.x;
        o1.y = (a1.y - mu) * rstd * gm1.y + bt1.y;
        o1.z = (a1.z - mu) * rstd * gm1.z + bt1.z;
        o1.w = (a1.w - mu) * rstd * gm1.w + bt1.w;

        *(float4*)(out + (base + tg) * NO + lane * 4) = o0;
        *(float4*)(out + (base + tg) * NO + 128 + lane * 4) = o1;
    }
}

// ---------------------------------------------------------------------------
extern "C" void kernel_launch(void* const* d_in, const int* in_sizes, int n_in,
                              void* d_out, int out_size)
{
    const float* x   = (const float*)d_in[0];
    const float* Wq  = (const float*)d_in[1];
    const float* Wk  = (const float*)d_in[2];
    const float* Wv  = (const float*)d_in[3];
    const float* Wqs = (const float*)d_in[4];
    const float* Wks = (const float*)d_in[5];
    const float* Wvs = (const float*)d_in[6];
    const float* lq1 = (const float*)d_in[7];
    const float* lq2 = (const float*)d_in[8];
    const float* lk1 = (const float*)d_in[9];
    const float* lk2 = (const float*)d_in[10];
    const float* gam = (const float*)d_in[11];
    const float* bet = (const float*)d_in[12];

    qkv_gemm<<<dim3(12, 256), dim3(16, 16)>>>(x, Wq, Wk, Wv);
    state_fixup<<<64, 256>>>(x, Wqs, Wks, Wvs);
    lambda_kernel<<<1, 32>>>(lq1, lq2, lk1, lk2);

    const int smem_bytes = SM_TOTAL_F4 * (int)sizeof(float4);
    cudaFuncSetAttribute(attn_kernel,
                         cudaFuncAttributeMaxDynamicSharedMemorySize, smem_bytes);
    attn_kernel<<<dim3(TT / 16, BB), 256, smem_bytes>>>((float*)d_out, gam, bet);
}

// round 2
// speedup vs baseline: 1.0002x; 1.0002x over previous
#include <cuda_runtime.h>
#include <math.h>

#define BB 4
#define TT 4096
#define DD 1024
#define NO 256      // 2*dv
#define NROW (BB*TT)
#define LN_EPS_F 1e-5f
#define LAMBDA_INIT 0.3555090675909693f
#define ATT_SCALE 0.0883883476483184405f   // 1/sqrt(128)

// scratch (device globals: allocation-free rule)
__device__ float g_Q[NROW * NO];
__device__ float g_K[NROW * NO];
__device__ float g_V[NROW * NO];
__device__ float g_lambda;

// ---------------------------------------------------------------------------
// Kernel 1: uniform QKV GEMM.  C[16384 x 768] = X[16384 x 1024] @ {Wq|Wk|Wv}
// BM=64 BN=64 BK=16, 256 threads, 4x4 micro-tile.
// ---------------------------------------------------------------------------
__global__ __launch_bounds__(256) void qkv_gemm(
    const float* __restrict__ x,
    const float* __restrict__ Wq,
    const float* __restrict__ Wk,
    const float* __restrict__ Wv)
{
    __shared__ float Xs[16][68];   // [k][m], padded
    __shared__ float Ws[16][64];   // [k][n]

    const int nt  = blockIdx.x;          // 0..11
    const int mt  = blockIdx.y;          // 0..255
    const int mat = nt >> 2;             // 0=Q,1=K,2=V
    const int n0  = (nt & 3) * 64;
    const float* W = (mat == 0) ? Wq : ((mat == 1) ? Wk : Wv);
    float* Out     = (mat == 0) ? g_Q : ((mat == 1) ? g_K : g_V);

    const int m0 = mt * 64;
    const int tx = threadIdx.x;          // 0..15
    const int ty = threadIdx.y;          // 0..15
    const int tid = ty * 16 + tx;

    float c[4][4];
#pragma unroll
    for (int i = 0; i < 4; i++)
#pragma unroll
        for (int j = 0; j < 4; j++) c[i][j] = 0.f;

    for (int k0 = 0; k0 < DD; k0 += 16) {
        // X tile: 64 rows x 16 cols
        {
            int row = tid >> 2;          // 0..63
            int c4  = tid & 3;           // 0..3
            float4 xv = *(const float4*)(x + (size_t)(m0 + row) * DD + k0 + c4 * 4);
            Xs[c4 * 4 + 0][row] = xv.x;
            Xs[c4 * 4 + 1][row] = xv.y;
            Xs[c4 * 4 + 2][row] = xv.z;
            Xs[c4 * 4 + 3][row] = xv.w;
        }
        // W tile: 16 rows x 64 cols
        {
            int kr = tid >> 4;           // 0..15
            int c4 = tid & 15;           // 0..15
            float4 wv = *(const float4*)(W + (size_t)(k0 + kr) * NO + n0 + c4 * 4);
            *(float4*)(&Ws[kr][c4 * 4]) = wv;
        }
        __syncthreads();

#pragma unroll
        for (int kk = 0; kk < 16; kk++) {
            float4 a = *(const float4*)(&Xs[kk][ty * 4]);
            float4 b = *(const float4*)(&Ws[kk][tx * 4]);
            c[0][0] += a.x * b.x; c[0][1] += a.x * b.y; c[0][2] += a.x * b.z; c[0][3] += a.x * b.w;
            c[1][0] += a.y * b.x; c[1][1] += a.y * b.y; c[1][2] += a.y * b.z; c[1][3] += a.y * b.w;
            c[2][0] += a.z * b.x; c[2][1] += a.z * b.y; c[2][2] += a.z * b.z; c[2][3] += a.z * b.w;
            c[3][0] += a.w * b.x; c[3][1] += a.w * b.y; c[3][2] += a.w * b.z; c[3][3] += a.w * b.w;
        }
        __syncthreads();
    }

#pragma unroll
    for (int i = 0; i < 4; i++) {
        float4 o = make_float4(c[i][0], c[i][1], c[i][2], c[i][3]);
        *(float4*)(Out + (size_t)(m0 + ty * 4 + i) * NO + n0 + tx * 4) = o;
    }
}

// ---------------------------------------------------------------------------
// Kernel 2: recompute the 64 state rows (first/last 8 tokens per batch)
// with the *_state weights.
// ---------------------------------------------------------------------------
__global__ __launch_bounds__(256) void state_fixup(
    const float* __restrict__ x,
    const float* __restrict__ Wqs,
    const float* __restrict__ Wks,
    const float* __restrict__ Wvs)
{
    __shared__ float xs[DD];
    const int id = blockIdx.x;             // 0..63
    const int b  = id >> 4;
    const int i  = id & 15;
    const int t  = (i < 8) ? i : (TT - 16 + i);
    const size_t row = (size_t)b * TT + t;
    const int tid = threadIdx.x;           // 0..255

    for (int d = tid; d < DD; d += 256) xs[d] = x[row * DD + d];
    __syncthreads();

    float aq = 0.f, ak = 0.f, av = 0.f;
    const int n = tid;
#pragma unroll 4
    for (int d = 0; d < DD; d++) {
        float xv = xs[d];
        aq += xv * Wqs[(size_t)d * NO + n];
        ak += xv * Wks[(size_t)d * NO + n];
        av += xv * Wvs[(size_t)d * NO + n];
    }
    g_Q[row * NO + n] = aq;
    g_K[row * NO + n] = ak;
    g_V[row * NO + n] = av;
}

// ---------------------------------------------------------------------------
// Kernel 3: lambda scalar
// ---------------------------------------------------------------------------
__global__ void lambda_kernel(const float* __restrict__ lq1,
                              const float* __restrict__ lq2,
                              const float* __restrict__ lk1,
                              const float* __restrict__ lk2)
{
    int lane = threadIdx.x;
    float s1 = 0.f, s2 = 0.f;
    for (int i = lane; i < 128; i += 32) {
        s1 += lq1[i] * lk1[i];
        s2 += lq2[i] * lk2[i];
    }
#pragma unroll
    for (int o = 16; o > 0; o >>= 1) {
        s1 += __shfl_xor_sync(0xffffffffu, s1, o);
        s2 += __shfl_xor_sync(0xffffffffu, s2, o);
    }
    if (lane == 0) g_lambda = expf(s1) - expf(s2) + LAMBDA_INIT;
}

// ---------------------------------------------------------------------------
// Kernel 4: fused differential causal attention + combine + LayerNorm.
// CTA = 256 threads (8 warps), 16 query rows (2 per warp), 32-key chunks.
// ---------------------------------------------------------------------------
__device__ __forceinline__ void fma4(float4& a, float w, const float4& v) {
    a.x += w * v.x; a.y += w * v.y; a.z += w * v.z; a.w += w * v.w;
}
__device__ __forceinline__ void scale4(float4& a, float c) {
    a.x *= c; a.y *= c; a.z *= c; a.w *= c;
}

// smem layout (float4 units): qs[16*64] | ks[32*65] | vs[32*64]
#define SM_QS 0
#define SM_KS (16 * 64)
#define SM_VS (16 * 64 + 32 * 65)
#define SM_TOTAL_F4 (16 * 64 + 32 * 65 + 32 * 64)

__global__ __launch_bounds__(256, 2) void attn_kernel(
    float* __restrict__ out,
    const float* __restrict__ ln_gamma,
    const float* __restrict__ ln_beta)
{
    extern __shared__ float4 sm[];
    float4* qs = sm + SM_QS;
    float4* ks = sm + SM_KS;
    float4* vs = sm + SM_VS;

    const int b   = blockIdx.y;
    const int t0  = blockIdx.x * 16;
    const int tid = threadIdx.x;
    const int warp = tid >> 5;
    const int lane = tid & 31;
    const size_t base = (size_t)b * TT;

    // load Q tile (16 rows x 256 floats)
    for (int idx = tid; idx < 16 * 64; idx += 256) {
        int r  = idx >> 6;
        int d4 = idx & 63;
        qs[idx] = *(const float4*)(g_Q + (base + t0 + r) * NO + d4 * 4);
    }

    const int r0  = warp * 2;
    const int tg0 = t0 + r0;
    const int tg1 = tg0 + 1;

    float m[2][2], l[2][2];
    float4 acc[2][2][2];   // [head][row][half]
#pragma unroll
    for (int h = 0; h < 2; h++)
#pragma unroll
        for (int r = 0; r < 2; r++) {
            m[h][r] = -INFINITY;
            l[h][r] = 0.f;
            acc[h][r][0] = make_float4(0.f, 0.f, 0.f, 0.f);
            acc[h][r][1] = make_float4(0.f, 0.f, 0.f, 0.f);
        }

    const int nch = (t0 + 16 + 31) >> 5;
    for (int c = 0; c < nch; c++) {
        const int kb = c << 5;
        __syncthreads();
        // load K/V chunk (32 keys)
        for (int idx = tid; idx < 32 * 64; idx += 256) {
            int key = idx >> 6;
            int d4  = idx & 63;
            int kr  = kb + key;
            float4 kv, vv;
            if (kr < TT) {
                kv = *(const float4*)(g_K + (base + kr) * NO + d4 * 4);
                vv = *(const float4*)(g_V + (base + kr) * NO + d4 * 4);
            } else {
                kv = make_float4(0.f, 0.f, 0.f, 0.f);
                vv = kv;
            }
            ks[key * 65 + d4] = kv;
            vs[key * 64 + d4] = vv;
        }
        __syncthreads();

        if (kb <= tg1) {
            // scores for both heads, both rows
            float sc[2][2];
#pragma unroll
            for (int h = 0; h < 2; h++) {
                float s0 = 0.f, s1 = 0.f;
                const float4* kp  = ks + lane * 65 + h * 32;
                const float4* q0p = qs + r0 * 64 + h * 32;
                const float4* q1p = q0p + 64;
#pragma unroll
                for (int d4 = 0; d4 < 32; d4++) {
                    float4 kf = kp[d4];
                    float4 qa = q0p[d4];
                    float4 qb = q1p[d4];
                    s0 += kf.x * qa.x + kf.y * qa.y + kf.z * qa.z + kf.w * qa.w;
                    s1 += kf.x * qb.x + kf.y * qb.y + kf.z * qb.z + kf.w * qb.w;
                }
                sc[h][0] = s0 * ATT_SCALE;
                sc[h][1] = s1 * ATT_SCALE;
            }

            const int key = kb + lane;
            float pw[2][2];
#pragma unroll
            for (int h = 0; h < 2; h++) {
#pragma unroll
                for (int ri = 0; ri < 2; ri++) {
                    const int tg = ri ? tg1 : tg0;
                    float s = sc[h][ri];
                    if (key > tg) s = -INFINITY;
                    float wm = s;
#pragma unroll
                    for (int o = 16; o > 0; o >>= 1)
                        wm = fmaxf(wm, __shfl_xor_sync(0xffffffffu, wm, o));
                    if (kb <= tg) {
                        float newm = fmaxf(m[h][ri], wm);
                        float p    = __expf(s - newm);
                        float corr = __expf(m[h][ri] - newm);
                        float psum = p;
#pragma unroll
                        for (int o = 16; o > 0; o >>= 1)
                            psum += __shfl_xor_sync(0xffffffffu, psum, o);
                        l[h][ri] = l[h][ri] * corr + psum;
                        m[h][ri] = newm;
                        scale4(acc[h][ri][0], corr);
                        scale4(acc[h][ri][1], corr);
                        pw[h][ri] = p;
                    } else {
                        pw[h][ri] = 0.f;
                    }
                }
            }

            // P @ V, shared V reads across heads/rows
#pragma unroll 8
            for (int j = 0; j < 32; j++) {
                float4 v0 = vs[j * 64 + lane];
                float4 v1 = vs[j * 64 + 32 + lane];
                float w;
                w = __shfl_sync(0xffffffffu, pw[0][0], j);
                fma4(acc[0][0][0], w, v0); fma4(acc[0][0][1], w, v1);
                w = __shfl_sync(0xffffffffu, pw[0][1], j);
                fma4(acc[0][1][0], w, v0); fma4(acc[0][1][1], w, v1);
                w = __shfl_sync(0xffffffffu, pw[1][0], j);
                fma4(acc[1][0][0], w, v0); fma4(acc[1][0][1], w, v1);
                w = __shfl_sync(0xffffffffu, pw[1][1], j);
                fma4(acc[1][1][0], w, v0); fma4(acc[1][1][1], w, v1);
            }
        }
    }

    // epilogue: combine + LayerNorm
    const float lamv = g_lambda;
    const float4 gm0 = *(const float4*)(ln_gamma + lane * 4);
    const float4 gm1 = *(const float4*)(ln_gamma + 128 + lane * 4);
    const float4 bt0 = *(const float4*)(ln_beta + lane * 4);
    const float4 bt1 = *(const float4*)(ln_beta + 128 + lane * 4);

#pragma unroll
    for (int ri = 0; ri < 2; ri++) {
        const int tg = t0 + r0 + ri;
        float i1 = 1.f / l[0][ri];
        float i2 = lamv / l[1][ri];
        float4 a0, a1;
        a0.x = acc[0][ri][0].x * i1 - acc[1][ri][0].x * i2;
        a0.y = acc[0][ri][0].y * i1 - acc[1][ri][0].y * i2;
        a0.z = acc[0][ri][0].z * i1 - acc[1][ri][0].z * i2;
        a0.w = acc[0][ri][0].w * i1 - acc[1][ri][0].w * i2;
        a1.x = acc[0][ri][1].x * i1 - acc[1][ri][1].x * i2;
        a1.y = acc[0][ri][1].y * i1 - acc[1][ri][1].y * i2;
        a1.z = acc[0][ri][1].z * i1 - acc[1][ri][1].z * i2;
        a1.w = acc[0][ri][1].w * i1 - acc[1][ri][1].w * i2;

        float s = a0.x + a0.y + a0.z + a0.w + a1.x + a1.y + a1.z + a1.w;
#pragma unroll
        for (int o = 16; o > 0; o >>= 1) s += __shfl_xor_sync(0xffffffffu, s, o);
        float mu = s * (1.f / 256.f);

        float q = 0.f;
        q += (a0.x - mu) * (a0.x - mu); q += (a0.y - mu) * (a0.y - mu);
        q += (a0.z - mu) * (a0.z - mu); q += (a0.w - mu) * (a0.w - mu);
        q += (a1.x - mu) * (a1.x - mu); q += (a1.y - mu) * (a1.y - mu);
        q += (a1.z - mu) * (a1.z - mu); q += (a1.w - mu) * (a1.w - mu);
#pragma unroll
        for (int o = 16; o > 0; o >>= 1) q += __shfl_xor_sync(0xffffffffu, q, o);
        float var  = q * (1.f / 256.f);
        float rstd = rsqrtf(var + LN_EPS_F);

        float4 o0, o1;
        o0.x = (a0.x - mu) * rstd * gm0.x + bt0.x;
        o0.y = (a0.y - mu) * rstd * gm0.y + bt0.y;
        o0.z = (a0.z - mu) * rstd * gm0.z + bt0.z;
        o0.w = (a0.w - mu) * rstd * gm0.w + bt0.w;
        o1.x = (a1.x - mu) * rstd * gm1.x + bt1.x;
        o1.y = (a1.y - mu) * rstd * gm1.y + bt1.y;
        o1.z = (a1.z - mu) * rstd * gm1.z + bt1.z;
        o1.w = (a1.w - mu) * rstd * gm1.w + bt1.w;

        *(float4*)(out + (base + tg) * NO + lane * 4) = o0;
        *(float4*)(out + (base + tg) * NO + 128 + lane * 4) = o1;
    }
}

// ---------------------------------------------------------------------------
extern "C" void kernel_launch(void* const* d_in, const int* in_sizes, int n_in,
                              void* d_out, int out_size)
{
    const float* x   = (const float*)d_in[0];
    const float* Wq  = (const float*)d_in[1];
    const float* Wk  = (const float*)d_in[2];
    const float* Wv  = (const float*)d_in[3];
    const float* Wqs = (const float*)d_in[4];
    const float* Wks = (const float*)d_in[5];
    const float* Wvs = (const float*)d_in[6];
    const float* lq1 = (const float*)d_in[7];
    const float* lq2 = (const float*)d_in[8];
    const float* lk1 = (const float*)d_in[9];
    const float* lk2 = (const float*)d_in[10];
    const float* gam = (const float*)d_in[11];
    const float* bet = (const float*)d_in[12];

    qkv_gemm<<<dim3(12, 256), dim3(16, 16)>>>(x, Wq, Wk, Wv);
    state_fixup<<<64, 256>>>(x, Wqs, Wks, Wvs);
    lambda_kernel<<<1, 32>>>(lq1, lq2, lk1, lk2);

    const int smem_bytes = SM_TOTAL_F4 * (int)sizeof(float4);
    cudaFuncSetAttribute(attn_kernel,
                         cudaFuncAttributeMaxDynamicSharedMemorySize, smem_bytes);
    attn_kernel<<<dim3(TT / 16, BB), 256, smem_bytes>>>((float*)d_out, gam, bet);
}